// round 7
// baseline (speedup 1.0000x reference)
#include <cuda_runtime.h>
#include <math.h>

#define NN_MAX 100000
#define EE_MAX 1600000
#define DH 64

// ---------------- device scratch ----------------
__device__ float g_tmp[NN_MAX * DH];   // fp32 messages: (act(X) @ W^T) * dinv
__device__ float g_h[NN_MAX * DH];     // layer activations (pre-BN, post-bias)
__device__ float g_dinv[NN_MAX];
__device__ int   g_counts[NN_MAX];     // zeroed by scan3 after use (self-restoring)
__device__ int   g_rowptr[NN_MAX + 1];
__device__ int   g_cursor[NN_MAX];
__device__ int   g_esrc[EE_MAX];
__device__ int   g_blocksums[128];
__device__ float g_sums[DH];           // zeroed by stats_final after use
__device__ float g_sumsq[DH];
__device__ float g_scale[DH];
__device__ float g_shift[DH];

__device__ __forceinline__ float gelu_f(float v) {
    return 0.5f * v * (1.0f + erff(v * 0.70710678118654752440f));
}

// ---- packed f32x2 helpers (sm_103a FFMA2 path) ----
__device__ __forceinline__ unsigned long long pack2(float x, float y) {
    unsigned long long r;
    asm("mov.b64 %0, {%1, %2};" : "=l"(r) : "f"(x), "f"(y));
    return r;
}
__device__ __forceinline__ void fma2(unsigned long long& d, unsigned long long a,
                                     unsigned long long b) {
    asm("fma.rn.f32x2 %0, %1, %2, %0;" : "+l"(d) : "l"(a), "l"(b));
}
__device__ __forceinline__ float2 unpack2(unsigned long long v) {
    float2 f;
    asm("mov.b64 {%0, %1}, %2;" : "=f"(f.x), "=f"(f.y) : "l"(v));
    return f;
}

// ---------------- CSR build ----------------
__global__ void hist_kernel(const int* __restrict__ dst, int ee) {
    int e = blockIdx.x * blockDim.x + threadIdx.x;
    if (e < ee) atomicAdd(&g_counts[dst[e]], 1);
}

__global__ void scan1_kernel(int nn) {
    __shared__ int s[1024];
    int t = threadIdx.x;
    int i = blockIdx.x * 1024 + t;
    int c = (i < nn) ? g_counts[i] : 0;
    s[t] = c;
    __syncthreads();
    for (int off = 1; off < 1024; off <<= 1) {
        int v = (t >= off) ? s[t - off] : 0;
        __syncthreads();
        s[t] += v;
        __syncthreads();
    }
    if (i < nn) g_rowptr[i] = s[t];
    if (t == 1023) g_blocksums[blockIdx.x] = s[1023];
}

// merged scan2+scan3: finalize rowptr/cursor/dinv, zero counts for next call
__global__ void scan3_kernel(int nn, int ee, int nb) {
    __shared__ int bs[128];
    int t = threadIdx.x;
    if (t < 128) bs[t] = (t < nb) ? g_blocksums[t] : 0;
    __syncthreads();
    for (int off = 1; off < 128; off <<= 1) {
        int v = (t >= off && t < 128) ? bs[t - off] : 0;
        __syncthreads();
        if (t < 128) bs[t] += v;
        __syncthreads();
    }
    int base = (blockIdx.x == 0) ? 0 : bs[blockIdx.x - 1];

    int i = blockIdx.x * 1024 + t;
    if (i < nn) {
        int c = g_counts[i];
        g_counts[i] = 0;
        int excl = g_rowptr[i] - c + base;
        g_rowptr[i] = excl;
        g_cursor[i] = excl;
        g_dinv[i] = rsqrtf((float)(c + 1));  // +1 self loop
    }
    if (i == 0) g_rowptr[nn] = ee;
}

__global__ void fill_kernel(const int* __restrict__ src, const int* __restrict__ dst, int ee) {
    int e = blockIdx.x * blockDim.x + threadIdx.x;
    if (e < ee) {
        int pos = atomicAdd(&g_cursor[dst[e]], 1);
        g_esrc[pos] = src[e];
    }
}

// ---------------- GEMM: g_tmp[n,:] = (act(X)[n,:] @ W^T) * dinv[n] ----------------
// BM=128, BN=64, BK=32; 256 threads; 8x4 register tile (32 accum regs) for
// higher occupancy; FFMA2 packed along j.
template <int DIN, bool USE_GH, bool APPLY_ACT>
__global__ __launch_bounds__(256)
void gemm_scale_kernel(const float* __restrict__ Xin,
                       const float* __restrict__ W, int nn) {
    const float* __restrict__ X = USE_GH ? (const float*)g_h : Xin;

    __shared__ float Xs[32][132];  // [k][m], pad 4
    __shared__ float Ws[32][68];   // [k][j], pad 4
    __shared__ float s_sc[DH];
    __shared__ float s_sh[DH];

    int tid = threadIdx.x;
    int br = blockIdx.x * 128;
    int tx = tid & 15;   // col group: j0 = tx*4
    int ty = tid >> 4;   // row group: m0 = ty*8

    if (APPLY_ACT) {
        if (tid < DH) { s_sc[tid] = g_scale[tid]; s_sh[tid] = g_shift[tid]; }
        __syncthreads();
    }

    unsigned long long accp[8][2];
#pragma unroll
    for (int i = 0; i < 8; i++) { accp[i][0] = 0ULL; accp[i][1] = 0ULL; }

    for (int kb = 0; kb < DIN; kb += 32) {
        // X tile: thread -> row = tid>>1, k-half seg = tid&1 (16 floats), transposed store
        {
            int row = br + (tid >> 1);
            int seg = (tid & 1) * 16;
            bool ok = row < nn;
            const float* xr = X + (size_t)row * DIN + kb + seg;
#pragma unroll
            for (int kk = 0; kk < 4; kk++) {
                float4 v = ok ? *(const float4*)(xr + kk * 4)
                              : make_float4(0.f, 0.f, 0.f, 0.f);
                if (APPLY_ACT && ok) {
                    int k0 = kb + seg + kk * 4;
                    v.x = gelu_f(v.x * s_sc[k0 + 0] + s_sh[k0 + 0]);
                    v.y = gelu_f(v.y * s_sc[k0 + 1] + s_sh[k0 + 1]);
                    v.z = gelu_f(v.z * s_sc[k0 + 2] + s_sh[k0 + 2]);
                    v.w = gelu_f(v.w * s_sc[k0 + 3] + s_sh[k0 + 3]);
                }
                int r = tid >> 1;
                Xs[seg + kk * 4 + 0][r] = v.x;
                Xs[seg + kk * 4 + 1][r] = v.y;
                Xs[seg + kk * 4 + 2][r] = v.z;
                Xs[seg + kk * 4 + 3][r] = v.w;
            }
        }
        // W tile: thread -> j = tid&63, k-quarter = (tid>>6)*8, 2 float4
        {
            int j = tid & 63;
            int kh = (tid >> 6) * 8;
            const float* wr = W + (size_t)j * DIN + kb + kh;
#pragma unroll
            for (int kk = 0; kk < 2; kk++) {
                float4 v = *(const float4*)(wr + kk * 4);
                Ws[kh + kk * 4 + 0][j] = v.x;
                Ws[kh + kk * 4 + 1][j] = v.y;
                Ws[kh + kk * 4 + 2][j] = v.z;
                Ws[kh + kk * 4 + 3][j] = v.w;
            }
        }
        __syncthreads();

#pragma unroll 8
        for (int k = 0; k < 32; k++) {
            float4 a0 = *(const float4*)&Xs[k][ty * 8];
            float4 a1 = *(const float4*)&Xs[k][ty * 8 + 4];
            float4 b = *(const float4*)&Ws[k][tx * 4];
            unsigned long long bp0 = pack2(b.x, b.y);
            unsigned long long bp1 = pack2(b.z, b.w);
            float a[8] = {a0.x, a0.y, a0.z, a0.w, a1.x, a1.y, a1.z, a1.w};
#pragma unroll
            for (int i = 0; i < 8; i++) {
                unsigned long long ap = pack2(a[i], a[i]);
                fma2(accp[i][0], ap, bp0);
                fma2(accp[i][1], ap, bp1);
            }
        }
        __syncthreads();
    }

#pragma unroll
    for (int i = 0; i < 8; i++) {
        int row = br + ty * 8 + i;
        if (row < nn) {
            float dv = g_dinv[row];
            float2 p0 = unpack2(accp[i][0]);
            float2 p1 = unpack2(accp[i][1]);
            float4 r = make_float4(p0.x * dv, p0.y * dv, p1.x * dv, p1.y * dv);
            *(float4*)&g_tmp[(size_t)row * DH + tx * 4] = r;
        }
    }
}

// ---------------- gather-aggregate + bias + BN stats ----------------
// 2 nodes per warp: half-warp per node, lane owns a float4 (cols 4*lq..4*lq+3).
// One data LDG.128 serves one edge of EACH half -> 1 warp-LDG per edge total.
__global__ void gather_kernel(const float* __restrict__ bias, int nn) {
    __shared__ float ss[DH];
    __shared__ float sq[DH];
    int tid = threadIdx.x;
    if (tid < DH) { ss[tid] = 0.0f; sq[tid] = 0.0f; }
    __syncthreads();

    const float4* __restrict__ tmp4 = (const float4*)g_tmp;
    float4* __restrict__ h4 = (float4*)g_h;

    int lane = tid & 31;
    int half = lane >> 4;     // 0 or 1: which node of the pair
    int lq = lane & 15;       // float4 slot within the 64-col row

    int warp = blockIdx.x * (blockDim.x >> 5) + (tid >> 5);
    int nwarps = gridDim.x * (blockDim.x >> 5);

    float4 bv = ((const float4*)bias)[lq];
    float4 sacc = make_float4(0.f, 0.f, 0.f, 0.f);
    float4 qacc = make_float4(0.f, 0.f, 0.f, 0.f);

    for (int p = warp; 2 * p < nn; p += nwarps) {
        int n = 2 * p + half;
        bool act = n < nn;
        int st = 0, len = 0;
        if (act) {
            st = g_rowptr[n];
            len = g_rowptr[n + 1] - st;
        }
        float4 a = act ? tmp4[(size_t)n * 16 + lq] : make_float4(0.f, 0.f, 0.f, 0.f);

        int lenO = __shfl_xor_sync(0xffffffffu, len, 16);
        int maxlen = (len > lenO) ? len : lenO;

        for (int done = 0; done < maxlen; done += 8) {
#pragma unroll
            for (int u = 0; u < 8; u++) {
                bool v = (done + u) < len;
                int si = v ? g_esrc[st + done + u] : 0;  // uniform within half
                if (v) {
                    float4 t = tmp4[(size_t)si * 16 + lq];
                    a.x += t.x; a.y += t.y; a.z += t.z; a.w += t.w;
                }
            }
        }

        if (act) {
            float dv = g_dinv[n];
            float4 r = make_float4(a.x * dv + bv.x, a.y * dv + bv.y,
                                   a.z * dv + bv.z, a.w * dv + bv.w);
            h4[(size_t)n * 16 + lq] = r;
            sacc.x += r.x; sacc.y += r.y; sacc.z += r.z; sacc.w += r.w;
            qacc.x += r.x * r.x; qacc.y += r.y * r.y;
            qacc.z += r.z * r.z; qacc.w += r.w * r.w;
        }
    }

    atomicAdd(&ss[4 * lq + 0], sacc.x);
    atomicAdd(&ss[4 * lq + 1], sacc.y);
    atomicAdd(&ss[4 * lq + 2], sacc.z);
    atomicAdd(&ss[4 * lq + 3], sacc.w);
    atomicAdd(&sq[4 * lq + 0], qacc.x);
    atomicAdd(&sq[4 * lq + 1], qacc.y);
    atomicAdd(&sq[4 * lq + 2], qacc.z);
    atomicAdd(&sq[4 * lq + 3], qacc.w);
    __syncthreads();
    if (tid < DH) {
        atomicAdd(&g_sums[tid], ss[tid]);
        atomicAdd(&g_sumsq[tid], sq[tid]);
    }
}

// ---------------- BN stats -> scale/shift; re-zero stats ----------------
__global__ void stats_final_kernel(const float* __restrict__ gamma,
                                   const float* __restrict__ beta, float invN) {
    int j = threadIdx.x;  // 64 threads
    float mean = g_sums[j] * invN;
    float var = g_sumsq[j] * invN - mean * mean;
    float sc = gamma[j] * rsqrtf(var + 1e-5f);
    g_scale[j] = sc;
    g_shift[j] = beta[j] - mean * sc;
    g_sums[j] = 0.0f;
    g_sumsq[j] = 0.0f;
}

// ---------------- final: out = act(h) @ Wf^T + bf  (64 -> 10) ----------------
__global__ void final_kernel(const float* __restrict__ Wf, const float* __restrict__ bf,
                             float* __restrict__ out, int nn) {
    __shared__ float Hs[64][65];
    __shared__ float Ws[10][64];
    __shared__ float s_sc[DH];
    __shared__ float s_sh[DH];
    int tid = threadIdx.x;  // 128 threads
    int br = blockIdx.x * 64;

    if (tid < DH) { s_sc[tid] = g_scale[tid]; s_sh[tid] = g_shift[tid]; }
    __syncthreads();

    for (int idx = tid; idx < 64 * 64; idx += 128) {
        int n = idx >> 6, k = idx & 63;
        int row = br + n;
        float v = (row < nn) ? g_h[row * DH + k] : 0.0f;
        Hs[n][k] = gelu_f(v * s_sc[k] + s_sh[k]);
    }
    for (int idx = tid; idx < 640; idx += 128) {
        Ws[idx >> 6][idx & 63] = Wf[idx];
    }
    __syncthreads();

    int nl = tid & 63;
    int c0 = (tid >> 6) * 5;
    float acc[5];
#pragma unroll
    for (int c = 0; c < 5; c++) acc[c] = bf[c0 + c];
#pragma unroll 16
    for (int k = 0; k < 64; k++) {
        float hv = Hs[nl][k];
#pragma unroll
        for (int c = 0; c < 5; c++) acc[c] += hv * Ws[c0 + c][k];
    }
    int row = br + nl;
    if (row < nn) {
#pragma unroll
        for (int c = 0; c < 5; c++) out[row * 10 + c0 + c] = acc[c];
    }
}

// ---------------- host orchestration ----------------
extern "C" void kernel_launch(void* const* d_in, const int* in_sizes, int n_in,
                              void* d_out, int out_size) {
    const float* x  = (const float*)d_in[0];
    const int*   ei = (const int*)d_in[1];
    const float* W1 = (const float*)d_in[2];
    const float* b1 = (const float*)d_in[3];
    const float* g1 = (const float*)d_in[4];
    const float* be1 = (const float*)d_in[5];
    const float* W2 = (const float*)d_in[6];
    const float* b2 = (const float*)d_in[7];
    const float* g2 = (const float*)d_in[8];
    const float* be2 = (const float*)d_in[9];
    const float* W3 = (const float*)d_in[10];
    const float* b3 = (const float*)d_in[11];
    const float* g3 = (const float*)d_in[12];
    const float* be3 = (const float*)d_in[13];
    const float* Wf = (const float*)d_in[14];
    const float* bf = (const float*)d_in[15];
    float* out = (float*)d_out;

    int nn = in_sizes[0] / 128;      // 100000
    int ee = in_sizes[1] / 2;        // 1600000
    const int* src = ei;
    const int* dst = ei + ee;

    int nb_e = (ee + 255) / 256;
    int nb_scan = (nn + 1023) / 1024;
    float invN = 1.0f / (float)nn;

    int gemm_blocks = (nn + 127) / 128;
    int out_blocks = (nn + 63) / 64;
    int gather_blocks = 1184;

    // ---- CSR build (counts/stats pre-zeroed: self-restoring invariants) ----
    hist_kernel<<<nb_e, 256>>>(dst, ee);
    scan1_kernel<<<nb_scan, 1024>>>(nn);
    scan3_kernel<<<nb_scan, 1024>>>(nn, ee, nb_scan);

    // ---- layer 1 (128 -> 64) ----
    gemm_scale_kernel<128, false, false><<<gemm_blocks, 256>>>(x, W1, nn);
    fill_kernel<<<nb_e, 256>>>(src, dst, ee);
    gather_kernel<<<gather_blocks, 256>>>(b1, nn);
    stats_final_kernel<<<1, 64>>>(g1, be1, invN);

    // ---- layer 2 (64 -> 64): BN1+GELU fused into X load ----
    gemm_scale_kernel<64, true, true><<<gemm_blocks, 256>>>(nullptr, W2, nn);
    gather_kernel<<<gather_blocks, 256>>>(b2, nn);
    stats_final_kernel<<<1, 64>>>(g2, be2, invN);

    // ---- layer 3 (64 -> 64): BN2+GELU fused into X load ----
    gemm_scale_kernel<64, true, true><<<gemm_blocks, 256>>>(nullptr, W3, nn);
    gather_kernel<<<gather_blocks, 256>>>(b3, nn);
    stats_final_kernel<<<1, 64>>>(g3, be3, invN);

    // ---- final classifier (64 -> 10): BN3+GELU fused into H load ----
    final_kernel<<<out_blocks, 128>>>(Wf, bf, out, nn);
}

// round 8
// speedup vs baseline: 1.2074x; 1.2074x over previous
#include <cuda_runtime.h>
#include <math.h>

#define NN_MAX 100000
#define EE_MAX 1600000
#define DH 64

// ---------------- device scratch ----------------
__device__ float g_tmp[NN_MAX * DH];   // fp32 messages: (act(X) @ W^T) * dinv
__device__ float g_h[NN_MAX * DH];     // layer activations (pre-BN, post-bias)
__device__ float g_dinv[NN_MAX];
__device__ int   g_counts[NN_MAX];     // zeroed by scan3 after use (self-restoring)
__device__ int   g_rowptr[NN_MAX + 1];
__device__ int   g_cursor[NN_MAX];
__device__ int   g_esrc[EE_MAX];
__device__ int   g_blocksums[128];
__device__ float g_sums[DH];           // zeroed by stats_final after use
__device__ float g_sumsq[DH];
__device__ float g_scale[DH];
__device__ float g_shift[DH];

__device__ __forceinline__ float gelu_f(float v) {
    return 0.5f * v * (1.0f + erff(v * 0.70710678118654752440f));
}

// ---- packed f32x2 helpers (sm_103a FFMA2 path) ----
__device__ __forceinline__ unsigned long long pack2(float x, float y) {
    unsigned long long r;
    asm("mov.b64 %0, {%1, %2};" : "=l"(r) : "f"(x), "f"(y));
    return r;
}
__device__ __forceinline__ void fma2(unsigned long long& d, unsigned long long a,
                                     unsigned long long b) {
    asm("fma.rn.f32x2 %0, %1, %2, %0;" : "+l"(d) : "l"(a), "l"(b));
}
__device__ __forceinline__ float2 unpack2(unsigned long long v) {
    float2 f;
    asm("mov.b64 {%0, %1}, %2;" : "=f"(f.x), "=f"(f.y) : "l"(v));
    return f;
}

// ---------------- CSR build ----------------
__global__ void hist_kernel(const int* __restrict__ dst, int ee) {
    int e = blockIdx.x * blockDim.x + threadIdx.x;
    if (e < ee) atomicAdd(&g_counts[dst[e]], 1);
}

__global__ void scan1_kernel(int nn) {
    __shared__ int s[1024];
    int t = threadIdx.x;
    int i = blockIdx.x * 1024 + t;
    int c = (i < nn) ? g_counts[i] : 0;
    s[t] = c;
    __syncthreads();
    for (int off = 1; off < 1024; off <<= 1) {
        int v = (t >= off) ? s[t - off] : 0;
        __syncthreads();
        s[t] += v;
        __syncthreads();
    }
    if (i < nn) g_rowptr[i] = s[t];
    if (t == 1023) g_blocksums[blockIdx.x] = s[1023];
}

// merged scan2+scan3: finalize rowptr/cursor/dinv, zero counts for next call
__global__ void scan3_kernel(int nn, int ee, int nb) {
    __shared__ int bs[128];
    int t = threadIdx.x;
    if (t < 128) bs[t] = (t < nb) ? g_blocksums[t] : 0;
    __syncthreads();
    for (int off = 1; off < 128; off <<= 1) {
        int v = (t >= off && t < 128) ? bs[t - off] : 0;
        __syncthreads();
        if (t < 128) bs[t] += v;
        __syncthreads();
    }
    int base = (blockIdx.x == 0) ? 0 : bs[blockIdx.x - 1];

    int i = blockIdx.x * 1024 + t;
    if (i < nn) {
        int c = g_counts[i];
        g_counts[i] = 0;
        int excl = g_rowptr[i] - c + base;
        g_rowptr[i] = excl;
        g_cursor[i] = excl;
        g_dinv[i] = rsqrtf((float)(c + 1));  // +1 self loop
    }
    if (i == 0) g_rowptr[nn] = ee;
}

__global__ void fill_kernel(const int* __restrict__ src, const int* __restrict__ dst, int ee) {
    int e = blockIdx.x * blockDim.x + threadIdx.x;
    if (e < ee) {
        int pos = atomicAdd(&g_cursor[dst[e]], 1);
        g_esrc[pos] = src[e];
    }
}

// ---------------- GEMM: g_tmp[n,:] = (act(X)[n,:] @ W^T) * dinv[n] ----------------
// BM=128, BN=64, BK=32; 256 threads; 8x4 register tile; FFMA2 packed along j.
template <int DIN, bool USE_GH, bool APPLY_ACT>
__global__ __launch_bounds__(256)
void gemm_scale_kernel(const float* __restrict__ Xin,
                       const float* __restrict__ W, int nn) {
    const float* __restrict__ X = USE_GH ? (const float*)g_h : Xin;

    __shared__ float Xs[32][132];  // [k][m], pad 4
    __shared__ float Ws[32][68];   // [k][j], pad 4
    __shared__ float s_sc[DH];
    __shared__ float s_sh[DH];

    int tid = threadIdx.x;
    int br = blockIdx.x * 128;
    int tx = tid & 15;   // col group: j0 = tx*4
    int ty = tid >> 4;   // row group: m0 = ty*8

    if (APPLY_ACT) {
        if (tid < DH) { s_sc[tid] = g_scale[tid]; s_sh[tid] = g_shift[tid]; }
        __syncthreads();
    }

    unsigned long long accp[8][2];
#pragma unroll
    for (int i = 0; i < 8; i++) { accp[i][0] = 0ULL; accp[i][1] = 0ULL; }

    for (int kb = 0; kb < DIN; kb += 32) {
        // X tile: thread -> row = tid>>1, k-half seg = tid&1 (16 floats), transposed store
        {
            int row = br + (tid >> 1);
            int seg = (tid & 1) * 16;
            bool ok = row < nn;
            const float* xr = X + (size_t)row * DIN + kb + seg;
#pragma unroll
            for (int kk = 0; kk < 4; kk++) {
                float4 v = ok ? *(const float4*)(xr + kk * 4)
                              : make_float4(0.f, 0.f, 0.f, 0.f);
                if (APPLY_ACT && ok) {
                    int k0 = kb + seg + kk * 4;
                    v.x = gelu_f(v.x * s_sc[k0 + 0] + s_sh[k0 + 0]);
                    v.y = gelu_f(v.y * s_sc[k0 + 1] + s_sh[k0 + 1]);
                    v.z = gelu_f(v.z * s_sc[k0 + 2] + s_sh[k0 + 2]);
                    v.w = gelu_f(v.w * s_sc[k0 + 3] + s_sh[k0 + 3]);
                }
                int r = tid >> 1;
                Xs[seg + kk * 4 + 0][r] = v.x;
                Xs[seg + kk * 4 + 1][r] = v.y;
                Xs[seg + kk * 4 + 2][r] = v.z;
                Xs[seg + kk * 4 + 3][r] = v.w;
            }
        }
        // W tile: thread -> j = tid&63, k-quarter = (tid>>6)*8, 2 float4
        {
            int j = tid & 63;
            int kh = (tid >> 6) * 8;
            const float* wr = W + (size_t)j * DIN + kb + kh;
#pragma unroll
            for (int kk = 0; kk < 2; kk++) {
                float4 v = *(const float4*)(wr + kk * 4);
                Ws[kh + kk * 4 + 0][j] = v.x;
                Ws[kh + kk * 4 + 1][j] = v.y;
                Ws[kh + kk * 4 + 2][j] = v.z;
                Ws[kh + kk * 4 + 3][j] = v.w;
            }
        }
        __syncthreads();

#pragma unroll 8
        for (int k = 0; k < 32; k++) {
            float4 a0 = *(const float4*)&Xs[k][ty * 8];
            float4 a1 = *(const float4*)&Xs[k][ty * 8 + 4];
            float4 b = *(const float4*)&Ws[k][tx * 4];
            unsigned long long bp0 = pack2(b.x, b.y);
            unsigned long long bp1 = pack2(b.z, b.w);
            float a[8] = {a0.x, a0.y, a0.z, a0.w, a1.x, a1.y, a1.z, a1.w};
#pragma unroll
            for (int i = 0; i < 8; i++) {
                unsigned long long ap = pack2(a[i], a[i]);
                fma2(accp[i][0], ap, bp0);
                fma2(accp[i][1], ap, bp1);
            }
        }
        __syncthreads();
    }

#pragma unroll
    for (int i = 0; i < 8; i++) {
        int row = br + ty * 8 + i;
        if (row < nn) {
            float dv = g_dinv[row];
            float2 p0 = unpack2(accp[i][0]);
            float2 p1 = unpack2(accp[i][1]);
            float4 r = make_float4(p0.x * dv, p0.y * dv, p1.x * dv, p1.y * dv);
            *(float4*)&g_tmp[(size_t)row * DH + tx * 4] = r;
        }
    }
}

// ---------------- gather-aggregate + bias + BN stats ----------------
// warp per node; lane owns columns (2*lane, 2*lane+1) as float2; 8-wide unroll
// with int4-vectorized index loads (1.25 LDG issues/edge instead of 2).
__global__ void gather_kernel(const float* __restrict__ bias, int nn) {
    __shared__ float ss[DH];
    __shared__ float sq[DH];
    int tid = threadIdx.x;
    if (tid < DH) { ss[tid] = 0.0f; sq[tid] = 0.0f; }
    __syncthreads();

    const float2* __restrict__ tmp2 = (const float2*)g_tmp;
    float2* __restrict__ h2 = (float2*)g_h;

    int lane = tid & 31;
    int warp = blockIdx.x * (blockDim.x >> 5) + (tid >> 5);
    int nwarps = gridDim.x * (blockDim.x >> 5);

    float bx = bias[2 * lane];
    float by = bias[2 * lane + 1];
    float s0 = 0.f, s1 = 0.f, q0 = 0.f, q1 = 0.f;

    for (int n = warp; n < nn; n += nwarps) {
        int st = g_rowptr[n];
        int en = g_rowptr[n + 1];
        float2 self = tmp2[n * 32 + lane];
        float ax = self.x, ay = self.y;
        int e = st;
        // prologue: advance to 16B-aligned index position
        for (; e < en && (e & 3); e++) {
            float2 v = tmp2[g_esrc[e] * 32 + lane];
            ax += v.x; ay += v.y;
        }
        // main: 8 edges per iter, indices via 2x int4
        for (; e + 8 <= en; e += 8) {
            int4 i0 = *(const int4*)&g_esrc[e];
            int4 i1 = *(const int4*)&g_esrc[e + 4];
            float2 v0 = tmp2[i0.x * 32 + lane];
            float2 v1 = tmp2[i0.y * 32 + lane];
            float2 v2 = tmp2[i0.z * 32 + lane];
            float2 v3 = tmp2[i0.w * 32 + lane];
            float2 v4 = tmp2[i1.x * 32 + lane];
            float2 v5 = tmp2[i1.y * 32 + lane];
            float2 v6 = tmp2[i1.z * 32 + lane];
            float2 v7 = tmp2[i1.w * 32 + lane];
            ax += ((v0.x + v1.x) + (v2.x + v3.x)) + ((v4.x + v5.x) + (v6.x + v7.x));
            ay += ((v0.y + v1.y) + (v2.y + v3.y)) + ((v4.y + v5.y) + (v6.y + v7.y));
        }
        // epilogue
        for (; e < en; e++) {
            float2 v = tmp2[g_esrc[e] * 32 + lane];
            ax += v.x; ay += v.y;
        }
        float dv = g_dinv[n];
        float rx = ax * dv + bx;
        float ry = ay * dv + by;
        h2[n * 32 + lane] = make_float2(rx, ry);
        s0 += rx; q0 += rx * rx;
        s1 += ry; q1 += ry * ry;
    }

    atomicAdd(&ss[2 * lane], s0);
    atomicAdd(&ss[2 * lane + 1], s1);
    atomicAdd(&sq[2 * lane], q0);
    atomicAdd(&sq[2 * lane + 1], q1);
    __syncthreads();
    if (tid < DH) {
        atomicAdd(&g_sums[tid], ss[tid]);
        atomicAdd(&g_sumsq[tid], sq[tid]);
    }
}

// ---------------- BN stats -> scale/shift; re-zero stats ----------------
__global__ void stats_final_kernel(const float* __restrict__ gamma,
                                   const float* __restrict__ beta, float invN) {
    int j = threadIdx.x;  // 64 threads
    float mean = g_sums[j] * invN;
    float var = g_sumsq[j] * invN - mean * mean;
    float sc = gamma[j] * rsqrtf(var + 1e-5f);
    g_scale[j] = sc;
    g_shift[j] = beta[j] - mean * sc;
    g_sums[j] = 0.0f;
    g_sumsq[j] = 0.0f;
}

// ---------------- final: out = act(h) @ Wf^T + bf  (64 -> 10) ----------------
__global__ void final_kernel(const float* __restrict__ Wf, const float* __restrict__ bf,
                             float* __restrict__ out, int nn) {
    __shared__ float Hs[64][65];
    __shared__ float Ws[10][64];
    __shared__ float s_sc[DH];
    __shared__ float s_sh[DH];
    int tid = threadIdx.x;  // 128 threads
    int br = blockIdx.x * 64;

    if (tid < DH) { s_sc[tid] = g_scale[tid]; s_sh[tid] = g_shift[tid]; }
    __syncthreads();

    for (int idx = tid; idx < 64 * 64; idx += 128) {
        int n = idx >> 6, k = idx & 63;
        int row = br + n;
        float v = (row < nn) ? g_h[row * DH + k] : 0.0f;
        Hs[n][k] = gelu_f(v * s_sc[k] + s_sh[k]);
    }
    for (int idx = tid; idx < 640; idx += 128) {
        Ws[idx >> 6][idx & 63] = Wf[idx];
    }
    __syncthreads();

    int nl = tid & 63;
    int c0 = (tid >> 6) * 5;
    float acc[5];
#pragma unroll
    for (int c = 0; c < 5; c++) acc[c] = bf[c0 + c];
#pragma unroll 16
    for (int k = 0; k < 64; k++) {
        float hv = Hs[nl][k];
#pragma unroll
        for (int c = 0; c < 5; c++) acc[c] += hv * Ws[c0 + c][k];
    }
    int row = br + nl;
    if (row < nn) {
#pragma unroll
        for (int c = 0; c < 5; c++) out[row * 10 + c0 + c] = acc[c];
    }
}

// ---------------- host orchestration ----------------
extern "C" void kernel_launch(void* const* d_in, const int* in_sizes, int n_in,
                              void* d_out, int out_size) {
    const float* x  = (const float*)d_in[0];
    const int*   ei = (const int*)d_in[1];
    const float* W1 = (const float*)d_in[2];
    const float* b1 = (const float*)d_in[3];
    const float* g1 = (const float*)d_in[4];
    const float* be1 = (const float*)d_in[5];
    const float* W2 = (const float*)d_in[6];
    const float* b2 = (const float*)d_in[7];
    const float* g2 = (const float*)d_in[8];
    const float* be2 = (const float*)d_in[9];
    const float* W3 = (const float*)d_in[10];
    const float* b3 = (const float*)d_in[11];
    const float* g3 = (const float*)d_in[12];
    const float* be3 = (const float*)d_in[13];
    const float* Wf = (const float*)d_in[14];
    const float* bf = (const float*)d_in[15];
    float* out = (float*)d_out;

    int nn = in_sizes[0] / 128;      // 100000
    int ee = in_sizes[1] / 2;        // 1600000
    const int* src = ei;
    const int* dst = ei + ee;

    int nb_e = (ee + 255) / 256;
    int nb_scan = (nn + 1023) / 1024;
    float invN = 1.0f / (float)nn;

    int gemm_blocks = (nn + 127) / 128;
    int out_blocks = (nn + 63) / 64;
    int gather_blocks = 1184;

    // ---- CSR build (counts/stats pre-zeroed: self-restoring invariants) ----
    hist_kernel<<<nb_e, 256>>>(dst, ee);
    scan1_kernel<<<nb_scan, 1024>>>(nn);
    scan3_kernel<<<nb_scan, 1024>>>(nn, ee, nb_scan);

    // ---- layer 1 (128 -> 64) ----
    gemm_scale_kernel<128, false, false><<<gemm_blocks, 256>>>(x, W1, nn);
    fill_kernel<<<nb_e, 256>>>(src, dst, ee);
    gather_kernel<<<gather_blocks, 256>>>(b1, nn);
    stats_final_kernel<<<1, 64>>>(g1, be1, invN);

    // ---- layer 2 (64 -> 64): BN1+GELU fused into X load ----
    gemm_scale_kernel<64, true, true><<<gemm_blocks, 256>>>(nullptr, W2, nn);
    gather_kernel<<<gather_blocks, 256>>>(b2, nn);
    stats_final_kernel<<<1, 64>>>(g2, be2, invN);

    // ---- layer 3 (64 -> 64): BN2+GELU fused into X load ----
    gemm_scale_kernel<64, true, true><<<gemm_blocks, 256>>>(nullptr, W3, nn);
    gather_kernel<<<gather_blocks, 256>>>(b3, nn);
    stats_final_kernel<<<1, 64>>>(g3, be3, invN);

    // ---- final classifier (64 -> 10): BN3+GELU fused into H load ----
    final_kernel<<<out_blocks, 128>>>(Wf, bf, out, nn);
}